// round 2
// baseline (speedup 1.0000x reference)
#include <cuda_runtime.h>

#define DIM 64
#define ROWS_PER_BLK 128
#define THREADS 256
#define P2 66   // XY row pitch in float2 units (even -> 16B-aligned rows)

// shared layout (dynamic):
//   XY  : float2[ROWS_PER_BLK * P2]   (x = X value, y = agg value)  67584 B
//   Ws  : float [64*64]                                             16384 B
//   W1s : float [64*64]                                             16384 B
//   bounds: int[2]
#define SMEM_BYTES (ROWS_PER_BLK * P2 * 8 + 2 * DIM * DIM * 4 + 16)

// ---------------------------------------------------------------------------
// packed f32x2 helpers (FFMA2 only reachable via PTX on sm_103a)
// ---------------------------------------------------------------------------
__device__ __forceinline__ unsigned long long pack2(float lo, float hi) {
    unsigned long long r;
    asm("mov.b64 %0, {%1,%2};" : "=l"(r) : "f"(lo), "f"(hi));
    return r;
}
__device__ __forceinline__ unsigned long long fma2(unsigned long long a,
                                                   unsigned long long b,
                                                   unsigned long long c) {
    unsigned long long d;
    asm("fma.rn.f32x2 %0, %1, %2, %3;" : "=l"(d) : "l"(a), "l"(b), "l"(c));
    return d;
}
__device__ __forceinline__ float2 unpack2(unsigned long long p) {
    float lo, hi;
    asm("mov.b64 {%0,%1}, %2;" : "=f"(lo), "=f"(hi) : "l"(p));
    return make_float2(lo, hi);
}

// ---------------------------------------------------------------------------
// warp-parallel lower_bound on sorted rows[]: first idx with rows[idx] >= key
// ---------------------------------------------------------------------------
__device__ __forceinline__ int warp_lower_bound(const int* __restrict__ rows,
                                                int E, int key) {
    const unsigned full = 0xffffffffu;
    int lane = threadIdx.x & 31;
    int lo = 0, hi = E;
    while (hi - lo > 32) {
        int step = (hi - lo) >> 5;                  // >= 1
        int idx = lo + (lane + 1) * step;
        int v = (idx < hi) ? __ldg(rows + idx) : 0x7fffffff;
        int cnt = __popc(__ballot_sync(full, v < key));
        int nlo = lo + cnt * step;
        int nhi = (cnt < 32) ? min(hi, lo + (cnt + 1) * step) : hi;
        lo = nlo; hi = nhi;
    }
    int idx = lo + lane;
    int v = (idx < hi) ? __ldg(rows + idx) : 0x7fffffff;
    return lo + __popc(__ballot_sync(full, v < key));
}

// ---------------------------------------------------------------------------
// One fused kernel: per-block edge aggregation into smem + dual GEMM
//   out = (segment_sum(X[col]) / dd1) @ W + X @ W1
// ---------------------------------------------------------------------------
__global__ __launch_bounds__(THREADS) void gcn_fused_kernel(
    const float* __restrict__ X,
    const float* __restrict__ W,
    const float* __restrict__ W1,
    const float* __restrict__ dd1,
    const int* __restrict__ rows,
    const int* __restrict__ cols,
    float* __restrict__ out,
    int N, int E) {
    extern __shared__ float smem[];
    float2* XY  = (float2*)smem;                         // [128][P2]
    float*  Ws  = smem + ROWS_PER_BLK * P2 * 2;          // [64*64]
    float*  W1s = Ws + DIM * DIM;                        // [64*64]
    int*    bnd = (int*)(W1s + DIM * DIM);               // [2]

    const int tid  = threadIdx.x;
    const int wid  = tid >> 5;
    const int lane = tid & 31;
    const int r0   = blockIdx.x * ROWS_PER_BLK;

    // ---- Phase A: binary searches (warps 0,1) + slab loads (all) ----------
    if (wid == 0) {
        int e = warp_lower_bound(rows, E, r0);
        if (lane == 0) bnd[0] = e;
    } else if (wid == 1) {
        int e = warp_lower_bound(rows, E, r0 + ROWS_PER_BLK);
        if (lane == 0) bnd[1] = e;
    }

    // W, W1 -> smem (2048 float4 total)
    for (int i = tid; i < (DIM * DIM) / 4; i += THREADS) {
        ((float4*)Ws)[i]  = __ldg((const float4*)W + i);
        ((float4*)W1s)[i] = __ldg((const float4*)W1 + i);
    }
    // X slab -> XY.x, zero XY.y (single pass, no separate zeroing)
    for (int idx = tid; idx < ROWS_PER_BLK * (DIM / 4); idx += THREADS) {
        int rr  = idx >> 4;           // 0..127
        int k4  = (idx & 15) * 4;     // 0,4,...,60
        int row = r0 + rr;
        float4 v = make_float4(0.f, 0.f, 0.f, 0.f);
        if (row < N) v = __ldg((const float4*)(X + (size_t)row * DIM + k4));
        float4* p = (float4*)(XY + rr * P2 + k4);
        p[0] = make_float4(v.x, 0.f, v.y, 0.f);
        p[1] = make_float4(v.z, 0.f, v.w, 0.f);
    }
    __syncthreads();

    // ---- Phase B: edge aggregation (register-segmented, sorted rows) ------
    {
        const int e_lo = bnd[0], e_hi = bnd[1];
        const int cnt = e_hi - e_lo;
        if (cnt > 0) {
            const int chunk = (cnt + 7) >> 3;         // 8 warps
            int base = e_lo + wid * chunk;
            int end  = min(base + chunk, e_hi);
            if (base < end) {
                const unsigned full = 0xffffffffu;
                float ax = 0.f, ay = 0.f;
                int cur = __ldg(rows + base);
                for (int e0 = base; e0 < end; e0 += 32) {
                    int n = min(32, end - e0);
                    int r = 0, c = 0;
                    if (lane < n) {
                        r = __ldg(rows + e0 + lane);
                        c = __ldg(cols + e0 + lane);
                    }
                    for (int i = 0; i < n; i++) {
                        int ri = __shfl_sync(full, r, i);
                        int ci = __shfl_sync(full, c, i);
                        if (ri != cur) {
                            float inv = 1.0f / __ldg(dd1 + cur);
                            float2* yp = XY + (cur - r0) * P2 + 2 * lane;
                            atomicAdd(&yp[0].y, ax * inv);
                            atomicAdd(&yp[1].y, ay * inv);
                            ax = 0.f; ay = 0.f;
                            cur = ri;
                        }
                        float2 v = __ldg((const float2*)(X + (size_t)ci * DIM) + lane);
                        ax += v.x;
                        ay += v.y;
                    }
                }
                float inv = 1.0f / __ldg(dd1 + cur);
                float2* yp = XY + (cur - r0) * P2 + 2 * lane;
                atomicAdd(&yp[0].y, ax * inv);
                atomicAdd(&yp[1].y, ay * inv);
            }
        }
    }
    __syncthreads();

    // ---- Phase C: dual GEMM with packed f32x2 FMA -------------------------
    // thread tile: 8 rows x 4 cols; 16 col-groups x 16 row-groups
    const int cq = tid & 15;
    const int rq = tid >> 4;
    const int c0 = cq * 4;
    const int rt = rq * 8;

    unsigned long long acc[8][2];
#pragma unroll
    for (int i = 0; i < 8; i++) { acc[i][0] = 0ull; acc[i][1] = 0ull; }

#pragma unroll 4
    for (int k = 0; k < DIM; k++) {
        float4 wv  = *(const float4*)(Ws  + k * DIM + c0);
        float4 w1v = *(const float4*)(W1s + k * DIM + c0);
        unsigned long long wp0 = pack2(wv.x,  wv.y);
        unsigned long long wp1 = pack2(wv.z,  wv.w);
        unsigned long long q0  = pack2(w1v.x, w1v.y);
        unsigned long long q1  = pack2(w1v.z, w1v.w);
#pragma unroll
        for (int i = 0; i < 8; i++) {
            float2 xy = XY[(rt + i) * P2 + k];
            unsigned long long yp = pack2(xy.y, xy.y);
            unsigned long long xp = pack2(xy.x, xy.x);
            acc[i][0] = fma2(yp, wp0, acc[i][0]);
            acc[i][1] = fma2(yp, wp1, acc[i][1]);
            acc[i][0] = fma2(xp, q0, acc[i][0]);
            acc[i][1] = fma2(xp, q1, acc[i][1]);
        }
    }

#pragma unroll
    for (int i = 0; i < 8; i++) {
        int row = r0 + rt + i;
        if (row < N) {
            float2 a = unpack2(acc[i][0]);
            float2 b = unpack2(acc[i][1]);
            *(float4*)(out + (size_t)row * DIM + c0) =
                make_float4(a.x, a.y, b.x, b.y);
        }
    }
}

// ---------------------------------------------------------------------------
extern "C" void kernel_launch(void* const* d_in, const int* in_sizes, int n_in,
                              void* d_out, int out_size) {
    const float* X    = (const float*)d_in[0];   // [N, 64]
    const float* W    = (const float*)d_in[1];   // [64, 64]
    const float* W1   = (const float*)d_in[2];   // [64, 64]
    const float* dd1  = (const float*)d_in[3];   // [N, 1]
    const int*   rows = (const int*)d_in[4];     // [E] sorted
    const int*   cols = (const int*)d_in[5];     // [E]
    float*       out  = (float*)d_out;           // [N, 64]

    int N = in_sizes[0] / DIM;
    int E = in_sizes[4];

    static int smem_set = 0;
    if (!smem_set) {
        cudaFuncSetAttribute(gcn_fused_kernel,
                             cudaFuncAttributeMaxDynamicSharedMemorySize,
                             SMEM_BYTES);
        smem_set = 1;
    }

    int nblocks = (N + ROWS_PER_BLK - 1) / ROWS_PER_BLK;
    gcn_fused_kernel<<<nblocks, THREADS, SMEM_BYTES>>>(
        X, W, W1, dd1, rows, cols, out, N, E);
}

// round 3
// speedup vs baseline: 3.2358x; 3.2358x over previous
#include <cuda_runtime.h>

#define N_NODES 100000
#define DIM 64
#define EPW 128        // edges per warp in aggregation
#define P 66           // smem row pitch (floats); even -> 8B-aligned float2 rows

// Scratch: aggY[i] = sum_{edges -> i} X[col]   (dd1 scaling applied in GEMM)
__device__ float g_aggY[(size_t)N_NODES * DIM];

// ---------------------------------------------------------------------------
// packed f32x2 helpers
// ---------------------------------------------------------------------------
__device__ __forceinline__ unsigned long long pack2(float lo, float hi) {
    unsigned long long r;
    asm("mov.b64 %0, {%1,%2};" : "=l"(r) : "f"(lo), "f"(hi));
    return r;
}
__device__ __forceinline__ unsigned long long fma2(unsigned long long a,
                                                   unsigned long long b,
                                                   unsigned long long c) {
    unsigned long long d;
    asm("fma.rn.f32x2 %0, %1, %2, %3;" : "=l"(d) : "l"(a), "l"(b), "l"(c));
    return d;
}
__device__ __forceinline__ float2 unpack2(unsigned long long p) {
    float lo, hi;
    asm("mov.b64 {%0,%1}, %2;" : "=f"(lo), "=f"(hi) : "l"(p));
    return make_float2(lo, hi);
}

// ---------------------------------------------------------------------------
// 1) zero scratch (graph replays -> must re-zero each call)
// ---------------------------------------------------------------------------
__global__ __launch_bounds__(512) void zero_aggY_kernel() {
    const int n4 = (N_NODES * DIM) / 4;
    for (int i = blockIdx.x * blockDim.x + threadIdx.x; i < n4;
         i += gridDim.x * blockDim.x) {
        ((float4*)g_aggY)[i] = make_float4(0.f, 0.f, 0.f, 0.f);
    }
}

// ---------------------------------------------------------------------------
// 2) edge aggregation: warp-segmented sum over sorted row_ids.
//    Each warp owns EPW consecutive edges; lane owns 2 of 64 features.
//    Inner loop batches 8 independent X-row loads (MLP=8) BEFORE the
//    warp-uniform segment logic; flush via vector atomicAdd(float2*).
// ---------------------------------------------------------------------------
__global__ __launch_bounds__(256) void agg_kernel(const float* __restrict__ X,
                                                  const int* __restrict__ rows,
                                                  const int* __restrict__ cols,
                                                  int E) {
    const unsigned full = 0xffffffffu;
    int warp = (blockIdx.x * blockDim.x + threadIdx.x) >> 5;
    int lane = threadIdx.x & 31;
    int base = warp * EPW;
    if (base >= E) return;
    int end = min(base + EPW, E);

    const float2* __restrict__ Xp = (const float2*)X;

    float ax = 0.f, ay = 0.f;
    int cur = __ldg(rows + base);

    for (int e0 = base; e0 < end; e0 += 32) {
        int n = min(32, end - e0);
        int r = 0, c = 0;
        if (lane < n) {
            r = __ldg(rows + e0 + lane);
            c = __ldg(cols + e0 + lane);
        }
        if (n == 32) {
#pragma unroll
            for (int s = 0; s < 4; s++) {
                int ri[8], ci[8];
                float2 v[8];
#pragma unroll
                for (int j = 0; j < 8; j++) {
                    ri[j] = __shfl_sync(full, r, s * 8 + j);
                    ci[j] = __shfl_sync(full, c, s * 8 + j);
                }
#pragma unroll
                for (int j = 0; j < 8; j++) {
                    v[j] = __ldg(Xp + (size_t)ci[j] * 32 + lane);
                }
#pragma unroll
                for (int j = 0; j < 8; j++) {
                    if (ri[j] != cur) {  // warp-uniform branch
                        float2* dst = (float2*)(g_aggY + (size_t)cur * DIM) + lane;
                        atomicAdd(dst, make_float2(ax, ay));
                        ax = 0.f; ay = 0.f;
                        cur = ri[j];
                    }
                    ax += v[j].x;
                    ay += v[j].y;
                }
            }
        } else {
            for (int i = 0; i < n; i++) {
                int ri = __shfl_sync(full, r, i);
                int ci = __shfl_sync(full, c, i);
                if (ri != cur) {
                    float2* dst = (float2*)(g_aggY + (size_t)cur * DIM) + lane;
                    atomicAdd(dst, make_float2(ax, ay));
                    ax = 0.f; ay = 0.f;
                    cur = ri;
                }
                float2 v = __ldg(Xp + (size_t)ci * 32 + lane);
                ax += v.x;
                ay += v.y;
            }
        }
    }
    float2* dst = (float2*)(g_aggY + (size_t)cur * DIM) + lane;
    atomicAdd(dst, make_float2(ax, ay));
}

// ---------------------------------------------------------------------------
// 3) fused dual GEMM: out = (aggY/dd1) @ W + X @ W1
//    64 rows/block, 256 threads, 4x4 thread tile, k-paired f32x2 FMA.
// ---------------------------------------------------------------------------
__global__ __launch_bounds__(256) void gemm_kernel(const float* __restrict__ X,
                                                   const float* __restrict__ W,
                                                   const float* __restrict__ W1,
                                                   const float* __restrict__ dd1,
                                                   float* __restrict__ out,
                                                   int N) {
    extern __shared__ float smem[];
    float* Xs  = smem;                  // [64][P]
    float* Ys  = Xs + 64 * P;           // [64][P]
    float* Ws  = Ys + 64 * P;           // [64][64]
    float* W1s = Ws + DIM * DIM;        // [64][64]

    const int tid  = threadIdx.x;
    const int row0 = blockIdx.x * 64;

    for (int i = tid; i < (DIM * DIM) / 4; i += 256) {
        ((float4*)Ws)[i]  = __ldg((const float4*)W + i);
        ((float4*)W1s)[i] = __ldg((const float4*)W1 + i);
    }

    for (int idx = tid; idx < 64 * 16; idx += 256) {
        int r   = idx >> 4;
        int k4  = (idx & 15) * 4;
        int row = row0 + r;
        float4 v = make_float4(0.f, 0.f, 0.f, 0.f);
        float4 u = make_float4(0.f, 0.f, 0.f, 0.f);
        if (row < N) {
            v = __ldg((const float4*)(X + (size_t)row * DIM + k4));
            u = __ldg((const float4*)(g_aggY + (size_t)row * DIM + k4));
            float inv = __frcp_rn(__ldg(dd1 + row));
            u.x *= inv; u.y *= inv; u.z *= inv; u.w *= inv;
        }
        float* xr = Xs + r * P + k4;
        xr[0] = v.x; xr[1] = v.y; xr[2] = v.z; xr[3] = v.w;
        float* yr = Ys + r * P + k4;
        yr[0] = u.x; yr[1] = u.y; yr[2] = u.z; yr[3] = u.w;
    }
    __syncthreads();

    const int cq = tid & 15;
    const int rq = tid >> 4;
    const int c0 = cq * 4;
    const int rt = rq * 4;

    // acc2[i][c]: f32x2 pair accumulating even-k / odd-k partial sums
    unsigned long long acc[4][4];
#pragma unroll
    for (int i = 0; i < 4; i++)
#pragma unroll
        for (int j = 0; j < 4; j++) acc[i][j] = 0ull;

#pragma unroll 4
    for (int k = 0; k < DIM; k += 2) {
        float4 wa = *(const float4*)(Ws  + k * DIM + c0);
        float4 wb = *(const float4*)(Ws  + (k + 1) * DIM + c0);
        float4 qa = *(const float4*)(W1s + k * DIM + c0);
        float4 qb = *(const float4*)(W1s + (k + 1) * DIM + c0);
        unsigned long long wp0 = pack2(wa.x, wb.x);
        unsigned long long wp1 = pack2(wa.y, wb.y);
        unsigned long long wp2 = pack2(wa.z, wb.z);
        unsigned long long wp3 = pack2(wa.w, wb.w);
        unsigned long long qp0 = pack2(qa.x, qb.x);
        unsigned long long qp1 = pack2(qa.y, qb.y);
        unsigned long long qp2 = pack2(qa.z, qb.z);
        unsigned long long qp3 = pack2(qa.w, qb.w);
#pragma unroll
        for (int i = 0; i < 4; i++) {
            float2 xv = *(const float2*)(Xs + (rt + i) * P + k);
            float2 yv = *(const float2*)(Ys + (rt + i) * P + k);
            unsigned long long xp = pack2(xv.x, xv.y);
            unsigned long long yp = pack2(yv.x, yv.y);
            acc[i][0] = fma2(yp, wp0, acc[i][0]);
            acc[i][1] = fma2(yp, wp1, acc[i][1]);
            acc[i][2] = fma2(yp, wp2, acc[i][2]);
            acc[i][3] = fma2(yp, wp3, acc[i][3]);
            acc[i][0] = fma2(xp, qp0, acc[i][0]);
            acc[i][1] = fma2(xp, qp1, acc[i][1]);
            acc[i][2] = fma2(xp, qp2, acc[i][2]);
            acc[i][3] = fma2(xp, qp3, acc[i][3]);
        }
    }

#pragma unroll
    for (int i = 0; i < 4; i++) {
        int row = row0 + rt + i;
        if (row < N) {
            float2 a0 = unpack2(acc[i][0]);
            float2 a1 = unpack2(acc[i][1]);
            float2 a2 = unpack2(acc[i][2]);
            float2 a3 = unpack2(acc[i][3]);
            *(float4*)(out + (size_t)row * DIM + c0) =
                make_float4(a0.x + a0.y, a1.x + a1.y, a2.x + a2.y, a3.x + a3.y);
        }
    }
}

// ---------------------------------------------------------------------------
extern "C" void kernel_launch(void* const* d_in, const int* in_sizes, int n_in,
                              void* d_out, int out_size) {
    const float* X    = (const float*)d_in[0];   // [N, 64]
    const float* W    = (const float*)d_in[1];   // [64, 64]
    const float* W1   = (const float*)d_in[2];   // [64, 64]
    const float* dd1  = (const float*)d_in[3];   // [N, 1]
    const int*   rows = (const int*)d_in[4];     // [E] sorted
    const int*   cols = (const int*)d_in[5];     // [E]
    float*       out  = (float*)d_out;           // [N, 64]

    int N = in_sizes[0] / DIM;
    int E = in_sizes[4];

    // 1) zero scratch
    zero_aggY_kernel<<<592, 512>>>();

    // 2) edge aggregation into g_aggY
    {
        int nwarps  = (E + EPW - 1) / EPW;
        int nblocks = (nwarps + 7) / 8;
        agg_kernel<<<nblocks, 256>>>(X, rows, cols, E);
    }

    // 3) dual GEMM -> out
    {
        int nblocks = (N + 63) / 64;
        size_t smem_bytes = (2 * 64 * P + 2 * 64 * 64) * sizeof(float);
        static int smem_set = 0;
        if (!smem_set) {
            cudaFuncSetAttribute(gemm_kernel,
                                 cudaFuncAttributeMaxDynamicSharedMemorySize,
                                 (int)smem_bytes);
            smem_set = 1;
        }
        gemm_kernel<<<nblocks, 256, smem_bytes>>>(X, W, W1, dd1, out, N);
    }
}